// round 1
// baseline (speedup 1.0000x reference)
#include <cuda_runtime.h>
#include <cstdint>

// HaarWaveletTopK on GB300 (sm_103a)
// x: (B=8, T=8192, F=512) fp32.
// out = [main (B,T,F) | detail (B,T,F)] concatenated.
//
// main[b, 2t, f] = main[b, 2t+1, f] = (e + o) * 0.5          (e = x[b,2t,f], o = x[b,2t+1,f])
// detail[b, 2t, f] = +hh, detail[b, 2t+1, f] = -hh, where hh = (e - o) * 0.5,
//   but kept only at the top-8 |e-o| positions per (b,f) column; zero elsewhere.

#define DIM_B 8
#define DIM_T 8192
#define DIM_T2 4096
#define DIM_F 512

#define FT 16                   // f-columns per block
#define TSEG 16                 // t-segments (threads per column)
#define NTHREADS (FT * TSEG)    // 256
#define PER_THREAD (DIM_T2 / TSEG)  // 256 t per thread
#define TOPK 8

__global__ __launch_bounds__(NTHREADS)
void haar_topk_kernel(const float* __restrict__ x,
                      float* __restrict__ out_main,
                      float* __restrict__ out_det)
{
    __shared__ float s_key[FT][TSEG * TOPK];
    __shared__ int   s_pay[FT][TSEG * TOPK];

    const int lane_f = threadIdx.x & (FT - 1);
    const int ts     = threadIdx.x >> 4;           // t-segment id, 0..15
    const int f      = blockIdx.x * FT + lane_f;
    const int b      = blockIdx.y;

    const float* __restrict__ xb = x        + (size_t)b * DIM_T * DIM_F;
    float* __restrict__ mb       = out_main + (size_t)b * DIM_T * DIM_F;
    float* __restrict__ db       = out_det  + (size_t)b * DIM_T * DIM_F;

    // Register-resident sorted (descending) top-8 of |e-o|, payload = (t<<1)|sign
    float key[TOPK];
    int   pay[TOPK];
#pragma unroll
    for (int j = 0; j < TOPK; ++j) { key[j] = -1.0f; pay[j] = 0; }

    const int t0 = ts * PER_THREAD;

#pragma unroll 4
    for (int i = 0; i < PER_THREAD; ++i) {
        const int t = t0 + i;
        const size_t re = (size_t)(2 * t) * DIM_F + f;   // even row
        const float e = xb[re];
        const float o = xb[re + DIM_F];

        const float low = (e + o) * 0.5f;
        const float h   = e - o;                          // proportional to x_high

        mb[re]          = low;
        mb[re + DIM_F]  = low;
        db[re]          = 0.0f;
        db[re + DIM_F]  = 0.0f;

        const float a = fabsf(h);
        if (a > key[TOPK - 1]) {
            key[TOPK - 1] = a;
            pay[TOPK - 1] = (t << 1) | (h < 0.0f ? 1 : 0);
#pragma unroll
            for (int j = TOPK - 1; j > 0; --j) {
                if (key[j] > key[j - 1]) {
                    float tk = key[j]; key[j] = key[j - 1]; key[j - 1] = tk;
                    int   tp = pay[j]; pay[j] = pay[j - 1]; pay[j - 1] = tp;
                }
            }
        }
    }

    // Publish per-thread candidates
#pragma unroll
    for (int j = 0; j < TOPK; ++j) {
        s_key[lane_f][ts * TOPK + j] = key[j];
        s_pay[lane_f][ts * TOPK + j] = pay[j];
    }
    __syncthreads();   // also orders our zero-stores before the scatter below

    // One thread per column merges 16 partial lists and scatters the sparse details
    if (ts == 0) {
        float bk[TOPK];
        int   bp[TOPK];
#pragma unroll
        for (int j = 0; j < TOPK; ++j) { bk[j] = -1.0f; bp[j] = 0; }

        for (int c = 0; c < TSEG * TOPK; ++c) {
            const float a = s_key[lane_f][c];
            if (a > bk[TOPK - 1]) {
                bk[TOPK - 1] = a;
                bp[TOPK - 1] = s_pay[lane_f][c];
#pragma unroll
                for (int j = TOPK - 1; j > 0; --j) {
                    if (bk[j] > bk[j - 1]) {
                        float tk = bk[j]; bk[j] = bk[j - 1]; bk[j - 1] = tk;
                        int   tp = bp[j]; bp[j] = bp[j - 1]; bp[j - 1] = tp;
                    }
                }
            }
        }

#pragma unroll
        for (int j = 0; j < TOPK; ++j) {
            const int t = bp[j] >> 1;
            float v = bk[j] * 0.5f;          // |e-o| * 0.5 == |high_half|
            if (bp[j] & 1) v = -v;           // restore sign of (e-o)
            const size_t r = (size_t)(2 * t) * DIM_F + f;
            db[r]         = v;
            db[r + DIM_F] = -v;
        }
    }
}

extern "C" void kernel_launch(void* const* d_in, const int* in_sizes, int n_in,
                              void* d_out, int out_size)
{
    const float* x = (const float*)d_in[0];
    float* out = (float*)d_out;
    const size_t N = (size_t)out_size / 2;   // elements in `main`

    dim3 grid(DIM_F / FT, DIM_B);
    haar_topk_kernel<<<grid, NTHREADS>>>(x, out, out + N);
}

// round 2
// speedup vs baseline: 1.1303x; 1.1303x over previous
#include <cuda_runtime.h>
#include <cstdint>

// HaarWaveletTopK on GB300 (sm_103a) — two-phase, high-occupancy version.
// x: (B=8, T=8192, F=512) fp32.
// out = [main (B,T,F) | detail (B,T,F)] concatenated.

#define DIM_B 8
#define DIM_T 8192
#define DIM_T2 4096
#define DIM_F 512

#define TOPK 8
#define NC 16                         // t-chunks per column
#define T_PER_CHUNK (DIM_T2 / NC)     // 256
#define FT 32                         // f-columns per block (== warp width)
#define TSEG 8                        // warps per block (t-segments within chunk)
#define NTHREADS (FT * TSEG)          // 256
#define T_PER_THREAD (T_PER_CHUNK / TSEG)  // 32

// Per-(b, chunk, j, f) partial top-8 candidates. 8*16*8*512 = 524288 entries.
__device__ float g_key[DIM_B * NC * TOPK * DIM_F];
__device__ int   g_pay[DIM_B * NC * TOPK * DIM_F];

// ---------------------------------------------------------------------------
// Kernel 1: Haar transform, dense outputs, per-chunk top-8 partials.
// ---------------------------------------------------------------------------
__global__ __launch_bounds__(NTHREADS)
void haar_pass1(const float* __restrict__ x,
                float* __restrict__ out_main,
                float* __restrict__ out_det)
{
    __shared__ float s_key[FT][TSEG * TOPK + 1];   // +1 pad: kill bank conflicts
    __shared__ int   s_pay[FT][TSEG * TOPK + 1];

    const int lane_f = threadIdx.x & (FT - 1);     // 0..31, consecutive f in warp
    const int ts     = threadIdx.x >> 5;           // warp id = t-segment, 0..7
    const int f      = blockIdx.x * FT + lane_f;
    const int b      = blockIdx.y;
    const int c      = blockIdx.z;                 // chunk id, 0..NC-1

    const float* __restrict__ xb = x        + (size_t)b * DIM_T * DIM_F;
    float* __restrict__ mb       = out_main + (size_t)b * DIM_T * DIM_F;
    float* __restrict__ db       = out_det  + (size_t)b * DIM_T * DIM_F;

    float key[TOPK];
    int   pay[TOPK];
#pragma unroll
    for (int j = 0; j < TOPK; ++j) { key[j] = -1.0f; pay[j] = 0; }

    const int t0 = c * T_PER_CHUNK + ts * T_PER_THREAD;

#pragma unroll 4
    for (int i = 0; i < T_PER_THREAD; ++i) {
        const int t = t0 + i;
        const size_t re = (size_t)(2 * t) * DIM_F + f;   // even row
        const float e = xb[re];
        const float o = xb[re + DIM_F];

        const float low = (e + o) * 0.5f;
        const float h   = e - o;                          // ∝ x_high

        mb[re]          = low;
        mb[re + DIM_F]  = low;
        db[re]          = 0.0f;
        db[re + DIM_F]  = 0.0f;

        const float a = fabsf(h);
        if (a > key[TOPK - 1]) {
            key[TOPK - 1] = a;
            pay[TOPK - 1] = (t << 1) | (h < 0.0f ? 1 : 0);
#pragma unroll
            for (int j = TOPK - 1; j > 0; --j) {
                if (key[j] > key[j - 1]) {
                    float tk = key[j]; key[j] = key[j - 1]; key[j - 1] = tk;
                    int   tp = pay[j]; pay[j] = pay[j - 1]; pay[j - 1] = tp;
                }
            }
        }
    }

    // Publish per-thread candidates
#pragma unroll
    for (int j = 0; j < TOPK; ++j) {
        s_key[lane_f][ts * TOPK + j] = key[j];
        s_pay[lane_f][ts * TOPK + j] = pay[j];
    }
    __syncthreads();

    // Warp 0: one thread per column merges the 64 candidates, spills top-8.
    if (ts == 0) {
        float bk[TOPK];
        int   bp[TOPK];
#pragma unroll
        for (int j = 0; j < TOPK; ++j) { bk[j] = -1.0f; bp[j] = 0; }

#pragma unroll 4
        for (int q = 0; q < TSEG * TOPK; ++q) {
            const float a = s_key[lane_f][q];
            if (a > bk[TOPK - 1]) {
                bk[TOPK - 1] = a;
                bp[TOPK - 1] = s_pay[lane_f][q];
#pragma unroll
                for (int j = TOPK - 1; j > 0; --j) {
                    if (bk[j] > bk[j - 1]) {
                        float tk = bk[j]; bk[j] = bk[j - 1]; bk[j - 1] = tk;
                        int   tp = bp[j]; bp[j] = bp[j - 1]; bp[j - 1] = tp;
                    }
                }
            }
        }

        const size_t base = ((size_t)(b * NC + c) * TOPK) * DIM_F + f;
#pragma unroll
        for (int j = 0; j < TOPK; ++j) {
            g_key[base + (size_t)j * DIM_F] = bk[j];   // coalesced across lane_f
            g_pay[base + (size_t)j * DIM_F] = bp[j];
        }
    }
}

// ---------------------------------------------------------------------------
// Kernel 2: per-column merge of NC partial lists + sparse scatter into detail.
// One thread per (b, f) column. 4096 threads total.
// ---------------------------------------------------------------------------
__global__ __launch_bounds__(256)
void haar_pass2(float* __restrict__ out_det)
{
    const int idx = blockIdx.x * blockDim.x + threadIdx.x;   // 0..B*F-1
    const int b = idx / DIM_F;
    const int f = idx % DIM_F;                               // lanes: consecutive f

    float bk[TOPK];
    int   bp[TOPK];
#pragma unroll
    for (int j = 0; j < TOPK; ++j) { bk[j] = -1.0f; bp[j] = 0; }

    const size_t cbase = ((size_t)b * NC * TOPK) * DIM_F + f;
#pragma unroll 4
    for (int q = 0; q < NC * TOPK; ++q) {
        const float a = g_key[cbase + (size_t)q * DIM_F];    // coalesced
        if (a > bk[TOPK - 1]) {
            bk[TOPK - 1] = a;
            bp[TOPK - 1] = g_pay[cbase + (size_t)q * DIM_F];
#pragma unroll
            for (int j = TOPK - 1; j > 0; --j) {
                if (bk[j] > bk[j - 1]) {
                    float tk = bk[j]; bk[j] = bk[j - 1]; bk[j - 1] = tk;
                    int   tp = bp[j]; bp[j] = bp[j - 1]; bp[j - 1] = tp;
                }
            }
        }
    }

    float* __restrict__ db = out_det + (size_t)b * DIM_T * DIM_F;
#pragma unroll
    for (int j = 0; j < TOPK; ++j) {
        const int t = bp[j] >> 1;
        float v = bk[j] * 0.5f;            // |e-o|*0.5 == |high_half|
        if (bp[j] & 1) v = -v;             // sign of (e-o)
        const size_t r = (size_t)(2 * t) * DIM_F + f;
        db[r]         = v;
        db[r + DIM_F] = -v;
    }
}

extern "C" void kernel_launch(void* const* d_in, const int* in_sizes, int n_in,
                              void* d_out, int out_size)
{
    const float* x = (const float*)d_in[0];
    float* out = (float*)d_out;
    const size_t N = (size_t)out_size / 2;   // elements in `main`

    dim3 grid1(DIM_F / FT, DIM_B, NC);
    haar_pass1<<<grid1, NTHREADS>>>(x, out, out + N);

    const int cols = DIM_B * DIM_F;          // 4096
    haar_pass2<<<cols / 256, 256>>>(out + N);
}

// round 3
// speedup vs baseline: 1.8361x; 1.6245x over previous
#include <cuda_runtime.h>
#include <cstdint>

// HaarWaveletTopK on GB300 (sm_103a) — float2-vectorized pass1 + warp-parallel pass2.
// x: (B=8, T=8192, F=512) fp32.  out = [main | detail], each (B,T,F).

#define DIM_B 8
#define DIM_T 8192
#define DIM_T2 4096
#define DIM_F 512
#define DIM_F2 (DIM_F / 2)            // 256 float2 per row

#define TOPK 8
#define NC 16                          // t-chunks per column
#define T_PER_CHUNK (DIM_T2 / NC)      // 256
#define TSEG 8                         // warps per block (t-split inside chunk)
#define NTHREADS (32 * TSEG)           // 256
#define T_PER_THREAD (T_PER_CHUNK / TSEG)  // 32
#define FBLK 64                        // f-columns per block (2 per thread-lane)
#define NCAND (NC * TOPK)              // 128 candidates per column

typedef unsigned long long u64;
typedef unsigned int u32;

// Packed candidates: [col][q], col = b*512+f, q = chunk*8+j.  4 MB.
__device__ u64 g_cand[DIM_B * DIM_F * NCAND];

__device__ __forceinline__ void topk_insert(float (&key)[TOPK], int (&pay)[TOPK],
                                            float a, int p)
{
    if (a > key[TOPK - 1]) {
        key[TOPK - 1] = a;
        pay[TOPK - 1] = p;
#pragma unroll
        for (int j = TOPK - 1; j > 0; --j) {
            if (key[j] > key[j - 1]) {
                float tk = key[j]; key[j] = key[j - 1]; key[j - 1] = tk;
                int   tp = pay[j]; pay[j] = pay[j - 1]; pay[j - 1] = tp;
            }
        }
    }
}

__device__ __forceinline__ u64 pack_cand(float k, int p)
{
    return ((u64)__float_as_uint(k) << 32) | (u32)p;
}

// ---------------------------------------------------------------------------
// Pass 1: Haar transform (dense main + zero detail) and per-chunk top-8.
// Thread owns 2 adjacent f-columns (one float2 lane).
// ---------------------------------------------------------------------------
__global__ __launch_bounds__(NTHREADS)
void haar_pass1(const float2* __restrict__ x2,
                float2* __restrict__ m2,
                float2* __restrict__ d2)
{
    __shared__ u64 s_cand[FBLK][TSEG * TOPK + 1];

    const int lane = threadIdx.x & 31;        // f-pair index within block
    const int ts   = threadIdx.x >> 5;        // warp id = t-segment
    const int b    = blockIdx.y;
    const int c    = blockIdx.z;
    const int fc   = blockIdx.x * 32 + lane;  // float2 column index (0..255)

    const float2* __restrict__ xb = x2 + (size_t)b * DIM_T * DIM_F2;
    float2* __restrict__ mb       = m2 + (size_t)b * DIM_T * DIM_F2;
    float2* __restrict__ db       = d2 + (size_t)b * DIM_T * DIM_F2;

    float k0[TOPK], k1[TOPK];
    int   p0[TOPK], p1[TOPK];
#pragma unroll
    for (int j = 0; j < TOPK; ++j) { k0[j] = 0.0f; p0[j] = 0; k1[j] = 0.0f; p1[j] = 0; }

    const int t0 = c * T_PER_CHUNK + ts * T_PER_THREAD;
    const float2 z2 = make_float2(0.0f, 0.0f);

#pragma unroll 4
    for (int i = 0; i < T_PER_THREAD; ++i) {
        const int t = t0 + i;
        const size_t re = (size_t)(2 * t) * DIM_F2 + fc;   // even row, float2 units
        const float2 e = __ldcs(&xb[re]);
        const float2 o = __ldcs(&xb[re + DIM_F2]);

        float2 low;
        low.x = (e.x + o.x) * 0.5f;
        low.y = (e.y + o.y) * 0.5f;
        const float hx = e.x - o.x;
        const float hy = e.y - o.y;

        __stcs(&mb[re],           low);
        __stcs(&mb[re + DIM_F2],  low);
        __stcs(&db[re],           z2);
        __stcs(&db[re + DIM_F2],  z2);

        topk_insert(k0, p0, fabsf(hx), (t << 1) | (hx < 0.0f ? 1 : 0));
        topk_insert(k1, p1, fabsf(hy), (t << 1) | (hy < 0.0f ? 1 : 0));
    }

    // Publish per-thread candidates for both owned columns
#pragma unroll
    for (int j = 0; j < TOPK; ++j) {
        s_cand[2 * lane][ts * TOPK + j]     = pack_cand(k0[j], p0[j]);
        s_cand[2 * lane + 1][ts * TOPK + j] = pack_cand(k1[j], p1[j]);
    }
    __syncthreads();

    // Warp 0: each lane merges its 2 columns (64 candidates each), spills top-8.
    if (ts == 0) {
#pragma unroll
        for (int half = 0; half < 2; ++half) {
            const int col_l = 2 * lane + half;
            u64 best[TOPK];
#pragma unroll
            for (int j = 0; j < TOPK; ++j) best[j] = 0;

#pragma unroll 4
            for (int q = 0; q < TSEG * TOPK; ++q) {
                const u64 v = s_cand[col_l][q];
                if (v > best[TOPK - 1]) {
                    best[TOPK - 1] = v;
#pragma unroll
                    for (int j = TOPK - 1; j > 0; --j) {
                        if (best[j] > best[j - 1]) {
                            u64 tv = best[j]; best[j] = best[j - 1]; best[j - 1] = tv;
                        }
                    }
                }
            }

            const int f = blockIdx.x * FBLK + col_l;
            const size_t base = ((size_t)(b * DIM_F + f)) * NCAND + (size_t)c * TOPK;
#pragma unroll
            for (int j = 0; j < TOPK; ++j)
                g_cand[base + j] = best[j];     // 64B contiguous run per column
        }
    }
}

// ---------------------------------------------------------------------------
// Pass 2: one warp per (b,f) column — merge 128 candidates, scatter 16 values.
// ---------------------------------------------------------------------------
__global__ __launch_bounds__(256)
void haar_pass2(float* __restrict__ out_det)
{
    const int wid_in_blk = threadIdx.x >> 5;
    const int lane       = threadIdx.x & 31;
    const int col        = blockIdx.x * 8 + wid_in_blk;   // 0..4095
    const int b          = col >> 9;
    const int f          = col & (DIM_F - 1);

    const size_t base = (size_t)col * NCAND;

    // Each lane: 4 coalesced candidate loads
    u64 v0 = g_cand[base + lane];
    u64 v1 = g_cand[base + lane + 32];
    u64 v2 = g_cand[base + lane + 64];
    u64 v3 = g_cand[base + lane + 96];

    // Sort 4 descending (network)
    u64 t;
    if (v0 < v1) { t = v0; v0 = v1; v1 = t; }
    if (v2 < v3) { t = v2; v2 = v3; v3 = t; }
    if (v0 < v2) { t = v0; v0 = v2; v2 = t; }
    if (v1 < v3) { t = v1; v1 = v3; v3 = t; }
    if (v1 < v2) { t = v1; v1 = v2; v2 = t; }

    u64 res = 0;   // lane r holds round-r winner
#pragma unroll
    for (int r = 0; r < TOPK; ++r) {
        u64 head = v0;
#pragma unroll
        for (int off = 16; off > 0; off >>= 1) {
            const u64 other = __shfl_xor_sync(0xFFFFFFFFu, head, off);
            if (other > head) head = other;
        }
        const bool mine = (v0 == head) && (head != 0);
        const unsigned m = __ballot_sync(0xFFFFFFFFu, mine);
        const int winner = __ffs(m) - 1;
        if (lane == winner) { v0 = v1; v1 = v2; v2 = v3; v3 = 0; }
        if (lane == r) res = head;
    }

    // Lanes 0..7 scatter the sparse detail values
    if (lane < TOPK) {
        const u32 payv = (u32)res;
        const float k  = __uint_as_float((u32)(res >> 32));
        float v        = k * 0.5f;                 // |e-o|*0.5 = |high_half|
        if (payv & 1) v = -v;
        const int tt   = payv >> 1;
        float* __restrict__ db = out_det + (size_t)b * DIM_T * DIM_F;
        const size_t r0 = (size_t)(2 * tt) * DIM_F + f;
        db[r0]         = v;
        db[r0 + DIM_F] = -v;
    }
}

extern "C" void kernel_launch(void* const* d_in, const int* in_sizes, int n_in,
                              void* d_out, int out_size)
{
    const float* x = (const float*)d_in[0];
    float* out = (float*)d_out;
    const size_t N = (size_t)out_size / 2;   // elements in `main`

    dim3 grid1(DIM_F / FBLK, DIM_B, NC);     // 8 x 8 x 16 = 1024 blocks
    haar_pass1<<<grid1, NTHREADS>>>((const float2*)x,
                                    (float2*)out,
                                    (float2*)(out + N));

    haar_pass2<<<DIM_B * DIM_F / 8, 256>>>(out + N);   // 512 blocks
}